// round 1
// baseline (speedup 1.0000x reference)
#include <cuda_runtime.h>

#define B_    8
#define F_IN  32
#define CN    256
#define M_    64
#define C_OUT 64
#define C_CAT 224   // (2*3+1)*32
#define KC    16
#define XS_STRIDE 36
#define WS_STRIDE 68

// Scratch: H[b][m][fc][c], fc in [0,224): piece p at fc=32p.
// pieces: 0=x^T, 1=x1_b0, 2=x2_b0, 3=x1_b1, 4=x2_b1, 5=x1_b2, 6=x2_b2
__device__ float g_H[(size_t)B_ * M_ * C_CAT * CN];

// ---------------- cp.async helpers ----------------
__device__ __forceinline__ void cp_async16(void* s, const void* g) {
    unsigned sa = (unsigned)__cvta_generic_to_shared(s);
    asm volatile("cp.async.cg.shared.global [%0], [%1], 16;\n" :: "r"(sa), "l"(g));
}
__device__ __forceinline__ void cp_commit() {
    asm volatile("cp.async.commit_group;\n");
}
template<int N> __device__ __forceinline__ void cp_wait() {
    asm volatile("cp.async.wait_group %0;\n" :: "n"(N));
}

// ---------------- Kernel 1: x[b,f,n,m] -> H[b][m][0..31][n] ----------------
__global__ __launch_bounds__(256) void k_transpose(const float* __restrict__ x) {
    int id = blockIdx.x;           // ((b*32 + f)*8 + nt)
    int nt = id & 7;
    int f  = (id >> 3) & 31;
    int b  = id >> 8;

    __shared__ float ts[32][65];
    int t  = threadIdx.x;
    int m  = t & 63;
    int nl = t >> 6;               // 0..3
    const float* xp = x + ((size_t)(b * F_IN + f) * CN + nt * 32) * M_;
#pragma unroll
    for (int i = 0; i < 8; ++i) {
        int r = nl + 4 * i;
        ts[r][m] = xp[(size_t)r * M_ + m];
    }
    __syncthreads();
    int nl2 = t & 31;
    int mg  = t >> 5;              // 0..7
#pragma unroll
    for (int i = 0; i < 8; ++i) {
        int mm = mg + 8 * i;
        g_H[((size_t)(b * M_ + mm) * C_CAT + f) * CN + nt * 32 + nl2] = ts[nl2][mm];
    }
}

// ---------------- fused nconv hop ----------------
// out[f][v] = sum_n xin[n][f] * A[n][v]   (32 x 256 = [32x256k] @ [256k x 256v])
__device__ __forceinline__ void hop(const float* __restrict__ Ag,  // A[b][m]: 256x256
                                    const float* __restrict__ xin, // smem [256][XS_STRIDE]
                                    float* __restrict__ As,        // smem 2*KC*256
                                    float acc[8][4],
                                    int fg, int vh, int tv)
{
#pragma unroll
    for (int i = 0; i < 8; ++i)
#pragma unroll
        for (int j = 0; j < 4; ++j) acc[i][j] = 0.0f;

    int t  = threadIdx.x;
    int lr = t >> 6;               // 0..3
    int lc = (t & 63) * 4;         // float4 column

    // prefetch chunk 0 into buffer 0
#pragma unroll
    for (int r = 0; r < 4; ++r)
        cp_async16(&As[(lr + 4 * r) * CN + lc], Ag + (size_t)(lr + 4 * r) * CN + lc);
    cp_commit();

    for (int ch = 0; ch < CN / KC; ++ch) {
        float* buf = As + (ch & 1) * (KC * CN);
        if (ch < CN / KC - 1) {
            float* nbuf = As + ((ch + 1) & 1) * (KC * CN);
            const float* Agc = Ag + (size_t)(ch + 1) * KC * CN;
#pragma unroll
            for (int r = 0; r < 4; ++r)
                cp_async16(&nbuf[(lr + 4 * r) * CN + lc], Agc + (size_t)(lr + 4 * r) * CN + lc);
            cp_commit();
            cp_wait<1>();
        } else {
            cp_wait<0>();
        }
        __syncthreads();
#pragma unroll
        for (int kk = 0; kk < KC; ++kk) {
            int n = ch * KC + kk;
            float4 x0 = *(const float4*)&xin[n * XS_STRIDE + 8 * fg];
            float4 x1 = *(const float4*)&xin[n * XS_STRIDE + 8 * fg + 4];
            float4 a  = *(const float4*)&buf[kk * CN + 128 * vh + 4 * tv];
            float xv[8] = {x0.x, x0.y, x0.z, x0.w, x1.x, x1.y, x1.z, x1.w};
            float av[4] = {a.x, a.y, a.z, a.w};
#pragma unroll
            for (int i = 0; i < 8; ++i)
#pragma unroll
                for (int j = 0; j < 4; ++j)
                    acc[i][j] = fmaf(xv[i], av[j], acc[i][j]);
        }
        __syncthreads();
    }
}

// ---------------- Kernel 2: fused double-hop nconv ----------------
// block = (base kb, b, m); computes x1 = x@A and x2 = x1@A, writes pieces.
__global__ __launch_bounds__(256, 2) void k_nconv(const float* __restrict__ b0,
                                                  const float* __restrict__ b1,
                                                  const float* __restrict__ b2)
{
    extern __shared__ float smem[];
    float* xs  = smem;                      // 256*36
    float* x1s = smem + 256 * XS_STRIDE;    // 256*36
    float* As  = x1s + 256 * XS_STRIDE;     // 2*KC*256

    int id = blockIdx.x;                    // 0..1535
    int kb = id >> 9;
    int bm = id & 511;
    const float* Ag = (kb == 0 ? b0 : (kb == 1 ? b1 : b2)) + (size_t)bm * (CN * CN);
    float* Hbm = g_H + (size_t)bm * (C_CAT * CN);

    int t  = threadIdx.x;
    int tv = t & 31;
    int tg = t >> 5;
    int fg = tg & 3;
    int vh = tg >> 2;

    // fill xs[n][f] from piece 0 (n = t)
    {
        const float* p0 = Hbm;
#pragma unroll
        for (int f = 0; f < 32; ++f)
            xs[t * XS_STRIDE + f] = p0[f * CN + t];
    }
    __syncthreads();

    float acc[8][4];

    // hop 1: x1 = x @ A
    hop(Ag, xs, As, acc, fg, vh, tv);
    {
        float* Hp = Hbm + (size_t)(32 * (1 + 2 * kb)) * CN;
#pragma unroll
        for (int j = 0; j < 4; ++j) {
            int v = 128 * vh + 4 * tv + j;
            float4 w0 = make_float4(acc[0][j], acc[1][j], acc[2][j], acc[3][j]);
            float4 w1 = make_float4(acc[4][j], acc[5][j], acc[6][j], acc[7][j]);
            *(float4*)&x1s[v * XS_STRIDE + 8 * fg]     = w0;
            *(float4*)&x1s[v * XS_STRIDE + 8 * fg + 4] = w1;
        }
#pragma unroll
        for (int i = 0; i < 8; ++i) {
            float4 w = make_float4(acc[i][0], acc[i][1], acc[i][2], acc[i][3]);
            *(float4*)&Hp[(8 * fg + i) * CN + 128 * vh + 4 * tv] = w;
        }
    }
    __syncthreads();

    // hop 2: x2 = x1 @ A  (A re-read, hits L2)
    hop(Ag, x1s, As, acc, fg, vh, tv);
    {
        float* Hp = Hbm + (size_t)(32 * (2 + 2 * kb)) * CN;
#pragma unroll
        for (int i = 0; i < 8; ++i) {
            float4 w = make_float4(acc[i][0], acc[i][1], acc[i][2], acc[i][3]);
            *(float4*)&Hp[(8 * fg + i) * CN + 128 * vh + 4 * tv] = w;
        }
    }
}

// ---------------- Kernel 3: y[b,o,c,m] = W[o,:] . H[b][m][:][c] + bias[o] ----------------
__global__ __launch_bounds__(256, 2) void k_final(const float* __restrict__ W,
                                                  const float* __restrict__ bias,
                                                  float* __restrict__ y)
{
    extern __shared__ float smem[];
    float* Ws = smem;                       // 224*68 transposed W: Ws[fc][o]
    float* Hs = Ws + C_CAT * WS_STRIDE;     // 2*KC*256

    int bm = blockIdx.x;
    int b  = bm >> 6;
    int m  = bm & 63;
    const float* Hbm = g_H + (size_t)bm * (C_CAT * CN);

    int t  = threadIdx.x;
    int tv = t & 31;
    int og = t >> 5;                        // 0..7

    int lr = t >> 6;
    int lc = (t & 63) * 4;

    // prefetch H chunk 0
#pragma unroll
    for (int r = 0; r < 4; ++r)
        cp_async16(&Hs[(lr + 4 * r) * CN + lc], Hbm + (size_t)(lr + 4 * r) * CN + lc);
    cp_commit();

    // fill Ws[fc][o]
    for (int i = t; i < C_OUT * C_CAT; i += 256) {
        int o = i / C_CAT, fc = i % C_CAT;
        Ws[fc * WS_STRIDE + o] = W[i];
    }
    float bv[8];
#pragma unroll
    for (int i = 0; i < 8; ++i) bv[i] = bias[8 * og + i];

    float acc[8][2][4];
#pragma unroll
    for (int i = 0; i < 8; ++i)
#pragma unroll
        for (int q = 0; q < 2; ++q)
#pragma unroll
            for (int j = 0; j < 4; ++j) acc[i][q][j] = 0.0f;

    const int NCH = C_CAT / KC;  // 14
    for (int ch = 0; ch < NCH; ++ch) {
        float* buf = Hs + (ch & 1) * (KC * CN);
        if (ch < NCH - 1) {
            float* nbuf = Hs + ((ch + 1) & 1) * (KC * CN);
            const float* Hc = Hbm + (size_t)(ch + 1) * KC * CN;
#pragma unroll
            for (int r = 0; r < 4; ++r)
                cp_async16(&nbuf[(lr + 4 * r) * CN + lc], Hc + (size_t)(lr + 4 * r) * CN + lc);
            cp_commit();
            cp_wait<1>();
        } else {
            cp_wait<0>();
        }
        __syncthreads();
#pragma unroll
        for (int kk = 0; kk < KC; ++kk) {
            int k = ch * KC + kk;
            float4 w0 = *(const float4*)&Ws[k * WS_STRIDE + 8 * og];
            float4 w1 = *(const float4*)&Ws[k * WS_STRIDE + 8 * og + 4];
            float4 h0 = *(const float4*)&buf[kk * CN + 4 * tv];
            float4 h1 = *(const float4*)&buf[kk * CN + 128 + 4 * tv];
            float wv[8]   = {w0.x, w0.y, w0.z, w0.w, w1.x, w1.y, w1.z, w1.w};
            float hv[2][4] = {{h0.x, h0.y, h0.z, h0.w}, {h1.x, h1.y, h1.z, h1.w}};
#pragma unroll
            for (int i = 0; i < 8; ++i)
#pragma unroll
                for (int q = 0; q < 2; ++q)
#pragma unroll
                    for (int j = 0; j < 4; ++j)
                        acc[i][q][j] = fmaf(wv[i], hv[q][j], acc[i][q][j]);
        }
        __syncthreads();
    }

    // scattered stores: y[((b*64+o)*256+c)*64 + m]
#pragma unroll
    for (int i = 0; i < 8; ++i) {
        int o = 8 * og + i;
        float bb = bv[i];
        size_t ob = ((size_t)(b * C_OUT + o) * CN) * M_ + m;
#pragma unroll
        for (int q = 0; q < 2; ++q)
#pragma unroll
            for (int j = 0; j < 4; ++j) {
                int c = 128 * q + 4 * tv + j;
                y[ob + (size_t)c * M_] = acc[i][q][j] + bb;
            }
    }
}

// ---------------- launch ----------------
extern "C" void kernel_launch(void* const* d_in, const int* in_sizes, int n_in,
                              void* d_out, int out_size) {
    const float* x    = (const float*)d_in[0];
    const float* b0   = (const float*)d_in[1];
    const float* b1   = (const float*)d_in[2];
    const float* b2   = (const float*)d_in[3];
    const float* W    = (const float*)d_in[4];
    const float* bias = (const float*)d_in[5];
    float* y = (float*)d_out;

    const int SMEM_K2 = (2 * 256 * XS_STRIDE + 2 * KC * CN) * 4;   // 106,496 B
    const int SMEM_K3 = (C_CAT * WS_STRIDE + 2 * KC * CN) * 4;     //  93,696 B
    cudaFuncSetAttribute(k_nconv, cudaFuncAttributeMaxDynamicSharedMemorySize, SMEM_K2);
    cudaFuncSetAttribute(k_final, cudaFuncAttributeMaxDynamicSharedMemorySize, SMEM_K3);

    k_transpose<<<2048, 256>>>(x);
    k_nconv<<<1536, 256, SMEM_K2>>>(b0, b1, b2);
    k_final<<<512, 256, SMEM_K3>>>(W, bias, y);
}